// round 4
// baseline (speedup 1.0000x reference)
#include <cuda_runtime.h>

// ---------------- device scratch (allocation-free: __device__ globals) -------
__device__ float g_stat1;            // conv1 input stat (scalar, C_in=1)
__device__ float g_stat2[64];        // conv2 input stat per channel
__device__ float g_stat3[1024];      // linear input stat per feature
__device__ float g_w1[1600];         // conv1 effective weights (64,1,5,5)
__device__ float g_b1[64];
// conv2 eff weights as splatted (w,w) pairs, co-contiguous padded to 26:
// idx = (ci*64 + co)*26 + j, j<25 valid, j=25 zero pad (16B alignment per co)
__device__ unsigned long long g_w2c[64 * 64 * 26];
__device__ float g_b2[64];
__device__ float g_wl[10240];        // linear eff weights (10,1024)
__device__ float g_bl[10];
__device__ __align__(16) float g_h1[2048 * 64 * 144]; // pooled conv1 output (N,64,12,12)
__device__ __align__(16) float g_h2[2048 * 1024];     // pooled conv2 output (N,1024)

// ---------------- helpers ----------------------------------------------------
__device__ __forceinline__ float scinol(float p0, float S2, float G, float eta,
                                        float M, bool cond) {
    float denom = sqrtf(S2 + M * M);
    float theta = fminf(fmaxf(G / denom, -1.0f), 1.0f);
    float upd = cond ? theta / (2.0f * denom) * eta : 0.0f;
    return p0 + upd;
}

__device__ __forceinline__ unsigned long long pk2(float v) {
    unsigned long long r;
    asm("mov.b64 %0, {%1, %2};" : "=l"(r) : "f"(v), "f"(v));
    return r;
}
__device__ __forceinline__ void fma2(unsigned long long& d, unsigned long long a,
                                     unsigned long long b) {
    asm("fma.rn.f32x2 %0, %1, %2, %0;" : "+l"(d) : "l"(a), "l"(b));
}
__device__ __forceinline__ void upk2(unsigned long long v, float& lo, float& hi) {
    asm("mov.b64 {%0, %1}, %2;" : "=f"(lo), "=f"(hi) : "l"(v));
}

// ---------------- kernel 0: zero stat accumulators ---------------------------
__global__ void zero_stats_kernel() {
    int i = threadIdx.x;
    if (i == 0) g_stat1 = 0.0f;
    if (i < 64) g_stat2[i] = 0.0f;
    if (i < 1024) g_stat3[i] = 0.0f;
}

// ---------------- kernel 1: stat1 = mean_n max_hw |x| ------------------------
__global__ void stat1_kernel(const float* __restrict__ x) {
    int n = blockIdx.x;
    const float* xs = x + n * 784;
    float m = 0.0f;
    for (int i = threadIdx.x; i < 784; i += 256) m = fmaxf(m, fabsf(xs[i]));
    __shared__ float red[8];
    #pragma unroll
    for (int o = 16; o; o >>= 1) m = fmaxf(m, __shfl_xor_sync(0xffffffffu, m, o));
    if ((threadIdx.x & 31) == 0) red[threadIdx.x >> 5] = m;
    __syncthreads();
    if (threadIdx.x < 8) {
        m = red[threadIdx.x];
        #pragma unroll
        for (int o = 4; o; o >>= 1) m = fmaxf(m, __shfl_xor_sync(0x000000ffu, m, o));
        if (threadIdx.x == 0) atomicAdd(&g_stat1, m * (1.0f / 2048.0f));
    }
}

// ---------------- kernel 2: conv1 effective params ---------------------------
__global__ void w1_kernel(const float* __restrict__ w0, const float* __restrict__ wS2,
                          const float* __restrict__ wG, const float* __restrict__ weta,
                          const float* __restrict__ wM, const float* __restrict__ b0,
                          const float* __restrict__ bS2, const float* __restrict__ bG,
                          const float* __restrict__ beta) {
    int i = blockIdx.x * 256 + threadIdx.x;
    if (i < 1600) {
        float M = fmaxf(g_stat1, wM[0]);  // C_in = 1
        g_w1[i] = scinol(w0[i], wS2[i], wG[i], weta[i], M, wG[i] != 0.0f);
    } else if (i < 1664) {
        int j = i - 1600;
        g_b1[j] = scinol(b0[j], bS2[j], bG[j], beta[j], 1.0f, bG[j] != 0.0f);
    }
}

// ---------------- kernel 3: conv1 + relu + pool + stat2 ----------------------
__global__ void __launch_bounds__(256) conv1_kernel(const float* __restrict__ x) {
    __shared__ float xs[784];
    __shared__ float ws[1600];
    __shared__ float bs[64];
    __shared__ unsigned int smax[64];
    int n = blockIdx.x;
    const float* xp = x + n * 784;
    for (int i = threadIdx.x; i < 784; i += 256) xs[i] = xp[i];
    for (int i = threadIdx.x; i < 1600; i += 256) ws[i] = g_w1[i];
    if (threadIdx.x < 64) { bs[threadIdx.x] = g_b1[threadIdx.x]; smax[threadIdx.x] = 0u; }
    __syncthreads();

    #pragma unroll 1
    for (int it = 0; it < 3; it++) {
        int task = threadIdx.x + it * 256;   // 768 tasks = 64 ch * 12 pooled rows
        int c = task / 12;
        int py = task % 12;
        float a0[24], a1[24];
        float b = bs[c];
        #pragma unroll
        for (int j = 0; j < 24; j++) { a0[j] = b; a1[j] = b; }
        const float* wc = ws + c * 25;
        #pragma unroll
        for (int i6 = 0; i6 < 6; i6++) {
            int iy = 2 * py + i6;            // input row, <= 27
            float4 xq[7];
            const float4* rp = (const float4*)(xs + iy * 28);
            #pragma unroll
            for (int j = 0; j < 7; j++) xq[j] = rp[j];
            const float* xr = (const float*)xq;
            if (i6 <= 4) {                   // conv row 2*py (ky=i6)
                #pragma unroll
                for (int kx = 0; kx < 5; kx++) {
                    float w = wc[i6 * 5 + kx];
                    #pragma unroll
                    for (int ox = 0; ox < 24; ox++) a0[ox] = fmaf(xr[ox + kx], w, a0[ox]);
                }
            }
            if (i6 >= 1) {                   // conv row 2*py+1 (ky=i6-1)
                #pragma unroll
                for (int kx = 0; kx < 5; kx++) {
                    float w = wc[(i6 - 1) * 5 + kx];
                    #pragma unroll
                    for (int ox = 0; ox < 24; ox++) a1[ox] = fmaf(xr[ox + kx], w, a1[ox]);
                }
            }
        }
        float rmax = 0.0f;
        float* hp = g_h1 + n * 9216 + c * 144 + py * 12;
        #pragma unroll
        for (int px = 0; px < 12; px++) {
            float v = fmaxf(fmaxf(a0[2 * px], a0[2 * px + 1]),
                            fmaxf(a1[2 * px], a1[2 * px + 1]));
            v = fmaxf(v, 0.0f);   // relu-then-pool == pool-then-relu
            hp[px] = v;
            rmax = fmaxf(rmax, v);
        }
        atomicMax(&smax[c], __float_as_uint(rmax));  // vals >= 0: bit order == fp order
    }
    __syncthreads();
    if (threadIdx.x < 64)
        atomicAdd(&g_stat2[threadIdx.x],
                  __uint_as_float(smax[threadIdx.x]) * (1.0f / 2048.0f));
}

// ---------------- kernel 4: conv2 effective params (co-contig padded pairs) --
__global__ void w2_kernel(const float* __restrict__ w0, const float* __restrict__ wS2,
                          const float* __restrict__ wG, const float* __restrict__ weta,
                          const float* __restrict__ wM, const float* __restrict__ b0,
                          const float* __restrict__ bS2, const float* __restrict__ bG,
                          const float* __restrict__ beta) {
    int idx = blockIdx.x * 256 + threadIdx.x;
    const int NW = 64 * 64 * 26;   // 106496
    if (idx < NW) {
        int j = idx % 26;
        int t = idx / 26;        // ci*64 + co
        int co = t & 63;
        int ci = t >> 6;
        float v = 0.0f;
        if (j < 25) {
            int src = co * 1600 + ci * 25 + j;
            float M = fmaxf(g_stat2[ci], wM[ci]);
            v = scinol(w0[src], wS2[src], wG[src], weta[src], M, wG[src] != 0.0f);
        }
        float2 p; p.x = v; p.y = v;
        ((float2*)g_w2c)[idx] = p;
    } else if (idx < NW + 64) {
        int j = idx - NW;
        g_b2[j] = scinol(b0[j], bS2[j], bG[j], beta[j], 1.0f, bG[j] != 0.0f);
    }
}

// ---------------- kernel 5: conv2 + relu + pool + stat3 ----------------------
// CTA = 2 samples, 256 threads (8 warps). warp = (sample, row-strip q2, co-half);
// lane = co. Each thread: 4 conv rows x 8 cols = 16 packed f32x2 accumulators.
// x loads warp-broadcast; weights per-thread as 13 conflict-free LDS.128 from a
// double-buffered 1-ci smem ring (prefetched through registers from global).
extern __shared__ float cs2[];
__global__ void __launch_bounds__(256) conv2_kernel() {
    float* xsA = cs2;                                   // 2*9216 floats
    float* xsB = cs2 + 18432;                           // 2*9216 floats (shift-1)
    unsigned long long* wring = (unsigned long long*)(cs2 + 36864);  // 2*1664 ull
    int tid = threadIdx.x;
    int n0 = blockIdx.x * 2;

    #pragma unroll
    for (int sl = 0; sl < 2; sl++) {
        const float* h1 = g_h1 + (n0 + sl) * 9216;
        float* xa = xsA + sl * 9216;
        float* xb = xsB + sl * 9216;
        for (int i = tid; i < 2304; i += 256)
            ((float4*)xa)[i] = ((const float4*)h1)[i];
        for (int i = tid; i < 9216; i += 256)
            xb[i] = (i < 9215) ? h1[i + 1] : 0.0f;
    }

    int w = tid >> 5, lane = tid & 31;
    int s  = w >> 2;            // sample within CTA
    int q2 = (w >> 1) & 1;      // row strip: conv rows 4*q2 .. 4*q2+3
    int co = (w & 1) * 32 + lane;

    const float* xa = xsA + s * 9216 + q2 * 48;   // input row base 4*q2 (*12 floats)
    const float* xb = xsB + s * 9216 + q2 * 48;

    unsigned long long acc[4][4];
    {
        unsigned long long bi = pk2(g_b2[co]);
        #pragma unroll
        for (int ro = 0; ro < 4; ro++)
            #pragma unroll
            for (int j = 0; j < 4; j++) acc[ro][j] = bi;
    }

    // prologue: stage-0 weight pairs into registers
    unsigned long long pf[7];
    #pragma unroll
    for (int k = 0; k < 7; k++) {
        int id = tid + k * 256;
        if (id < 1664) pf[k] = g_w2c[id];
    }

    #pragma unroll 1
    for (int ci = 0; ci < 64; ci++) {
        unsigned long long* wb = wring + (ci & 1) * 1664;
        #pragma unroll
        for (int k = 0; k < 7; k++) {
            int id = tid + k * 256;
            if (id < 1664) wb[id] = pf[k];
        }
        __syncthreads();
        if (ci < 63) {
            const unsigned long long* gw = g_w2c + (ci + 1) * 1664;
            #pragma unroll
            for (int k = 0; k < 7; k++) {
                int id = tid + k * 256;
                if (id < 1664) pf[k] = gw[id];
            }
        }

        // per-thread weights: 13 LDS.128, conflict-free (stride 52 words)
        unsigned long long wt[25];
        const ulonglong2* wp = (const ulonglong2*)(wb + co * 26);
        #pragma unroll
        for (int k = 0; k < 13; k++) {
            ulonglong2 v = wp[k];
            wt[2 * k] = v.x;
            if (2 * k + 1 < 25) wt[2 * k + 1] = v.y;
        }

        const float* bA = xa + ci * 144;
        const float* bB = xb + ci * 144;
        #pragma unroll
        for (int ir = 0; ir < 8; ir++) {     // input rows 4*q2 + ir
            ulonglong2 eA0 = *(const ulonglong2*)(bA + ir * 12);
            ulonglong2 eA1 = *(const ulonglong2*)(bA + ir * 12 + 4);
            ulonglong2 eA2 = *(const ulonglong2*)(bA + ir * 12 + 8);
            ulonglong2 eB0 = *(const ulonglong2*)(bB + ir * 12);
            ulonglong2 eB1 = *(const ulonglong2*)(bB + ir * 12 + 4);
            unsigned long long eB2 = *(const unsigned long long*)(bB + ir * 12 + 8);
            unsigned long long pe[6] = {eA0.x, eA0.y, eA1.x, eA1.y, eA2.x, eA2.y};
            unsigned long long po[5] = {eB0.x, eB0.y, eB1.x, eB1.y, eB2};
            #pragma unroll
            for (int ky = 0; ky < 5; ky++) {
                int ro = ir - ky;            // local conv row
                if (ro >= 0 && ro < 4) {
                    #pragma unroll
                    for (int kx = 0; kx < 5; kx++) {
                        const unsigned long long* src = (kx & 1) ? po : pe;
                        int h = kx >> 1;
                        unsigned long long ww = wt[ky * 5 + kx];
                        fma2(acc[ro][0], src[h + 0], ww);
                        fma2(acc[ro][1], src[h + 1], ww);
                        fma2(acc[ro][2], src[h + 2], ww);
                        fma2(acc[ro][3], src[h + 3], ww);
                    }
                }
            }
        }
    }

    // epilogue: 2x2 pool + relu entirely in-thread
    #pragma unroll
    for (int k = 0; k < 2; k++) {
        #pragma unroll
        for (int j = 0; j < 4; j++) {
            float a, b, c, d;
            upk2(acc[2 * k][j], a, b);
            upk2(acc[2 * k + 1][j], c, d);
            float p = fmaxf(fmaxf(a, b), fmaxf(c, d));
            p = fmaxf(p, 0.0f);
            int fb = co * 16 + (2 * q2 + k) * 4 + j;
            g_h2[(n0 + s) * 1024 + fb] = p;
            atomicAdd(&g_stat3[fb], p * (1.0f / 2048.0f));
        }
    }
}

// ---------------- kernel 6: linear effective params --------------------------
__global__ void wl_kernel(const float* __restrict__ w0, const float* __restrict__ wS2,
                          const float* __restrict__ wG, const float* __restrict__ weta,
                          const float* __restrict__ wM, const float* __restrict__ b0,
                          const float* __restrict__ bS2, const float* __restrict__ bG,
                          const float* __restrict__ beta) {
    int idx = blockIdx.x * 256 + threadIdx.x;
    if (idx < 10240) {
        int i = idx & 1023;
        float M = fmaxf(wM[idx], g_stat3[i]);
        // NOTE: linear weight cond is wS2 != 0 (not wG), per reference
        g_wl[idx] = scinol(w0[idx], wS2[idx], wG[idx], weta[idx], M, wS2[idx] != 0.0f);
    } else if (idx < 10250) {
        int j = idx - 10240;
        g_bl[j] = scinol(b0[j], bS2[j], bG[j], beta[j], 1.0f, bS2[j] != 0.0f);
    }
}

// ---------------- kernel 7: linear layer -------------------------------------
__global__ void __launch_bounds__(256) linear_kernel(float* __restrict__ out) {
    __shared__ float w_s[10240];
    __shared__ float b_s[16];
    for (int i = threadIdx.x; i < 10240; i += 256) w_s[i] = g_wl[i];
    if (threadIdx.x < 10) b_s[threadIdx.x] = g_bl[threadIdx.x];
    __syncthreads();
    int warp = threadIdx.x >> 5, lane = threadIdx.x & 31;
    for (int n = blockIdx.x * 8 + warp; n < 2048; n += 64 * 8) {
        const float* h = g_h2 + n * 1024;
        float hv[32];
        #pragma unroll
        for (int j = 0; j < 32; j++) hv[j] = h[lane + j * 32];
        #pragma unroll 1
        for (int o = 0; o < 10; o++) {
            float s = 0.0f;
            #pragma unroll
            for (int j = 0; j < 32; j++) s = fmaf(hv[j], w_s[o * 1024 + lane + j * 32], s);
            #pragma unroll
            for (int off = 16; off; off >>= 1) s += __shfl_xor_sync(0xffffffffu, s, off);
            if (lane == 0) out[n * 10 + o] = s + b_s[o];
        }
    }
}

// ---------------- launch ------------------------------------------------------
extern "C" void kernel_launch(void* const* d_in, const int* in_sizes, int n_in,
                              void* d_out, int out_size) {
    const float* x = (const float*)d_in[0];
    const float* c1[9]; for (int i = 0; i < 9; i++) c1[i] = (const float*)d_in[1 + i];
    const float* c2[9]; for (int i = 0; i < 9; i++) c2[i] = (const float*)d_in[10 + i];
    const float* lp[9]; for (int i = 0; i < 9; i++) lp[i] = (const float*)d_in[19 + i];
    float* out = (float*)d_out;

    // xsA + xsB (2 samples each) + double-buffered 1-ci weight ring
    const int conv2_smem = 36864 * 4 + 2 * 1664 * 8;  // 174080 B
    cudaFuncSetAttribute(conv2_kernel, cudaFuncAttributeMaxDynamicSharedMemorySize,
                         conv2_smem);

    zero_stats_kernel<<<1, 1024>>>();
    stat1_kernel<<<2048, 256>>>(x);
    w1_kernel<<<7, 256>>>(c1[0], c1[1], c1[2], c1[3], c1[4], c1[5], c1[6], c1[7], c1[8]);
    conv1_kernel<<<2048, 256>>>(x);
    w2_kernel<<<417, 256>>>(c2[0], c2[1], c2[2], c2[3], c2[4], c2[5], c2[6], c2[7], c2[8]);
    conv2_kernel<<<1024, 256, conv2_smem>>>();
    wl_kernel<<<41, 256>>>(lp[0], lp[1], lp[2], lp[3], lp[4], lp[5], lp[6], lp[7], lp[8]);
    linear_kernel<<<64, 256>>>(out);
}

// round 8
// speedup vs baseline: 1.0056x; 1.0056x over previous
#include <cuda_runtime.h>

// ---------------- device scratch (allocation-free: __device__ globals) -------
__device__ float g_stat1;            // conv1 input stat (scalar, C_in=1)
__device__ float g_stat2[64];        // conv2 input stat per channel
__device__ float g_stat3[1024];      // linear input stat per feature
__device__ float g_w1[1600];         // conv1 effective weights (64,1,5,5)
__device__ float g_b1[64];
// conv2 eff weights, splatted (w,w) pairs, ky-rows padded to 6:
// idx = ((ci*64 + co)*5 + ky)*6 + kx, kx<5 valid, kx=5 zero pad
__device__ unsigned long long g_w2r[64 * 64 * 5 * 6];
__device__ float g_b2[64];
__device__ float g_wl[10240];        // linear eff weights (10,1024)
__device__ float g_bl[10];
__device__ __align__(16) float g_h1[2048 * 64 * 144]; // pooled conv1 out (N,64,12,12)
__device__ __align__(16) float g_h2[2048 * 1024];     // pooled conv2 out (N,1024)

// ---------------- helpers ----------------------------------------------------
__device__ __forceinline__ float scinol(float p0, float S2, float G, float eta,
                                        float M, bool cond) {
    float denom = sqrtf(S2 + M * M);
    float theta = fminf(fmaxf(G / denom, -1.0f), 1.0f);
    float upd = cond ? theta / (2.0f * denom) * eta : 0.0f;
    return p0 + upd;
}

__device__ __forceinline__ unsigned long long pk2(float v) {
    unsigned long long r;
    asm("mov.b64 %0, {%1, %2};" : "=l"(r) : "f"(v), "f"(v));
    return r;
}
__device__ __forceinline__ void fma2(unsigned long long& d, unsigned long long a,
                                     unsigned long long b) {
    asm("fma.rn.f32x2 %0, %1, %2, %0;" : "+l"(d) : "l"(a), "l"(b));
}
__device__ __forceinline__ void upk2(unsigned long long v, float& lo, float& hi) {
    asm("mov.b64 {%0, %1}, %2;" : "=f"(lo), "=f"(hi) : "l"(v));
}

// ---------------- kernel 0: zero stat accumulators ---------------------------
__global__ void zero_stats_kernel() {
    int i = threadIdx.x;
    if (i == 0) g_stat1 = 0.0f;
    if (i < 64) g_stat2[i] = 0.0f;
    if (i < 1024) g_stat3[i] = 0.0f;
}

// ---------------- kernel 1: stat1 = mean_n max_hw |x| ------------------------
__global__ void stat1_kernel(const float* __restrict__ x) {
    int n = blockIdx.x;
    const float* xs = x + n * 784;
    float m = 0.0f;
    for (int i = threadIdx.x; i < 784; i += 256) m = fmaxf(m, fabsf(xs[i]));
    __shared__ float red[8];
    #pragma unroll
    for (int o = 16; o; o >>= 1) m = fmaxf(m, __shfl_xor_sync(0xffffffffu, m, o));
    if ((threadIdx.x & 31) == 0) red[threadIdx.x >> 5] = m;
    __syncthreads();
    if (threadIdx.x < 8) {
        m = red[threadIdx.x];
        #pragma unroll
        for (int o = 4; o; o >>= 1) m = fmaxf(m, __shfl_xor_sync(0x000000ffu, m, o));
        if (threadIdx.x == 0) atomicAdd(&g_stat1, m * (1.0f / 2048.0f));
    }
}

// ---------------- kernel 2: conv1 effective params ---------------------------
__global__ void w1_kernel(const float* __restrict__ w0, const float* __restrict__ wS2,
                          const float* __restrict__ wG, const float* __restrict__ weta,
                          const float* __restrict__ wM, const float* __restrict__ b0,
                          const float* __restrict__ bS2, const float* __restrict__ bG,
                          const float* __restrict__ beta) {
    int i = blockIdx.x * 256 + threadIdx.x;
    if (i < 1600) {
        float M = fmaxf(g_stat1, wM[0]);  // C_in = 1
        g_w1[i] = scinol(w0[i], wS2[i], wG[i], weta[i], M, wG[i] != 0.0f);
    } else if (i < 1664) {
        int j = i - 1600;
        g_b1[j] = scinol(b0[j], bS2[j], bG[j], beta[j], 1.0f, bG[j] != 0.0f);
    }
}

// ---------------- kernel 3: conv1 + relu + pool + stat2 (f32x2, broadcast) ---
// 1536 half-tasks per sample: task = (py, half, c); lanes differ in c only ->
// x LDS.64 loads are warp-broadcast. Each task: 2 conv rows x 12 cols packed.
// NOTE: xb (shift-1 copy) fill is SINGLE-WRITER (r4 had a write race here).
__global__ void __launch_bounds__(256) conv1_kernel(const float* __restrict__ x) {
    __shared__ float xs[788];
    __shared__ float xb[788];                 // shift-1 copy
    __shared__ unsigned long long wsp[1600];  // splatted (w,w) pairs
    __shared__ float bs[64];
    __shared__ unsigned int smax[64];
    int n = blockIdx.x;
    int tid = threadIdx.x;
    const float* xp = x + n * 784;
    for (int i = tid; i < 784; i += 256) {
        xs[i] = xp[i];
        xb[i] = (i < 783) ? xp[i + 1] : 0.0f;   // single writer per slot
    }
    for (int i = tid; i < 1600; i += 256) wsp[i] = pk2(g_w1[i]);
    if (tid < 64) { bs[tid] = g_b1[tid]; smax[tid] = 0u; }
    __syncthreads();

    #pragma unroll 1
    for (int it = 0; it < 6; it++) {
        int task = it * 256 + tid;           // 1536 tasks
        int c = task & 63;
        int r2i = task >> 6;                 // 0..23
        int py = r2i >> 1;                   // pooled row 0..11
        int hf = r2i & 1;                    // column half
        int base0 = 2 * py * 28 + hf * 12;

        unsigned long long A0[6], A1[6];
        {
            unsigned long long bi = pk2(bs[c]);
            #pragma unroll
            for (int j = 0; j < 6; j++) { A0[j] = bi; A1[j] = bi; }
        }
        const unsigned long long* wc = wsp + c * 25;
        unsigned long long wprev[5];
        #pragma unroll
        for (int i6 = 0; i6 < 6; i6++) {
            int base = base0 + i6 * 28;
            unsigned long long pe[8], po[7];
            #pragma unroll
            for (int k = 0; k < 8; k++)
                pe[k] = *(const unsigned long long*)(xs + base + 2 * k);
            #pragma unroll
            for (int k = 0; k < 7; k++)
                po[k] = *(const unsigned long long*)(xb + base + 2 * k);
            unsigned long long wcur[5];
            if (i6 <= 4) {
                #pragma unroll
                for (int kx = 0; kx < 5; kx++) wcur[kx] = wc[i6 * 5 + kx];
                #pragma unroll
                for (int kx = 0; kx < 5; kx++) {
                    const unsigned long long* src =
                        (kx & 1) ? (po + ((kx - 1) >> 1)) : (pe + (kx >> 1));
                    #pragma unroll
                    for (int j = 0; j < 6; j++) fma2(A0[j], src[j], wcur[kx]);
                }
            }
            if (i6 >= 1) {
                #pragma unroll
                for (int kx = 0; kx < 5; kx++) {
                    const unsigned long long* src =
                        (kx & 1) ? (po + ((kx - 1) >> 1)) : (pe + (kx >> 1));
                    #pragma unroll
                    for (int j = 0; j < 6; j++) fma2(A1[j], src[j], wprev[kx]);
                }
            }
            #pragma unroll
            for (int kx = 0; kx < 5; kx++) wprev[kx] = wcur[kx];
        }
        float rmax = 0.0f;
        float* hp = g_h1 + n * 9216 + c * 144 + py * 12 + hf * 6;
        #pragma unroll
        for (int j = 0; j < 6; j++) {
            float a, b, cc, d;
            upk2(A0[j], a, b);
            upk2(A1[j], cc, d);
            float v = fmaxf(fmaxf(a, b), fmaxf(cc, d));
            v = fmaxf(v, 0.0f);              // relu-then-pool == pool-then-relu
            hp[j] = v;
            rmax = fmaxf(rmax, v);
        }
        atomicMax(&smax[c], __float_as_uint(rmax));  // vals >= 0
    }
    __syncthreads();
    if (tid < 64)
        atomicAdd(&g_stat2[tid], __uint_as_float(smax[tid]) * (1.0f / 2048.0f));
}

// ---------------- kernel 4: conv2 effective params (padded ky-row pairs) -----
__global__ void w2_kernel(const float* __restrict__ w0, const float* __restrict__ wS2,
                          const float* __restrict__ wG, const float* __restrict__ weta,
                          const float* __restrict__ wM, const float* __restrict__ b0,
                          const float* __restrict__ bS2, const float* __restrict__ bG,
                          const float* __restrict__ beta) {
    int idx = blockIdx.x * 256 + threadIdx.x;
    const int NW = 64 * 64 * 5 * 6;   // 122880
    if (idx < NW) {
        int kx = idx % 6;
        int t = idx / 6;
        int ky = t % 5;
        int t2 = t / 5;          // ci*64 + co
        int co = t2 & 63;
        int ci = t2 >> 6;
        float v = 0.0f;
        if (kx < 5) {
            int src = co * 1600 + ci * 25 + ky * 5 + kx;
            float M = fmaxf(g_stat2[ci], wM[ci]);
            v = scinol(w0[src], wS2[src], wG[src], weta[src], M, wG[src] != 0.0f);
        }
        float2 p; p.x = v; p.y = v;
        ((float2*)g_w2r)[idx] = p;
    } else if (idx < NW + 64) {
        int j = idx - NW;
        g_b2[j] = scinol(b0[j], bS2[j], bG[j], beta[j], 1.0f, bG[j] != 0.0f);
    }
}

// ---------------- kernel 5: conv2 + relu + pool + stat3 ----------------------
// CTA = 2 samples, 512 threads (16 warps). warp = (sample, row-pair q, co-half);
// lane = co. x loads warp-broadcast; weights as padded 6-pair ky-rows -> each
// 5-pair row loads as 2x LDS.128 + 1x LDS.64, streamed wcur/wprev, from a
// double-buffered 2-ci smem ring prefetched through registers.
extern __shared__ float cs2[];
__global__ void __launch_bounds__(512) conv2_kernel() {
    float* xsA = cs2;                                   // 2*9216 floats
    float* xsB = cs2 + 18432;                           // 2*9216 floats (shift-1)
    unsigned long long* wring = (unsigned long long*)(cs2 + 36864);  // 2*3840 ull
    int tid = threadIdx.x;
    int n0 = blockIdx.x * 2;

    #pragma unroll
    for (int sl = 0; sl < 2; sl++) {
        const float* h1 = g_h1 + (n0 + sl) * 9216;
        float* xa = xsA + sl * 9216;
        float* xb = xsB + sl * 9216;
        for (int i = tid; i < 2304; i += 512)
            ((float4*)xa)[i] = ((const float4*)h1)[i];
        for (int i = tid; i < 9216; i += 512)
            xb[i] = (i < 9215) ? h1[i + 1] : 0.0f;
    }

    int w = tid >> 5, lane = tid & 31;
    int s = w >> 3;            // sample within CTA
    int q = (w >> 1) & 3;      // pooled row pair: conv rows 2q, 2q+1
    int co = (w & 1) * 32 + lane;

    const float* xa = xsA + s * 9216 + q * 24;
    const float* xb = xsB + s * 9216 + q * 24;

    unsigned long long a0[4], a1[4];
    {
        unsigned long long bi = pk2(g_b2[co]);
        #pragma unroll
        for (int j = 0; j < 4; j++) { a0[j] = bi; a1[j] = bi; }
    }

    // prologue: stage-0 (2 ci) weight pairs into registers
    unsigned long long pf[8];
    #pragma unroll
    for (int k = 0; k < 8; k++) {
        int id = tid + k * 512;
        if (id < 3840) pf[k] = g_w2r[id];
    }

    #pragma unroll 1
    for (int st = 0; st < 32; st++) {
        unsigned long long* wb = wring + (st & 1) * 3840;
        #pragma unroll
        for (int k = 0; k < 8; k++) {
            int id = tid + k * 512;
            if (id < 3840) wb[id] = pf[k];
        }
        __syncthreads();
        if (st < 31) {
            const unsigned long long* gw = g_w2r + (st + 1) * 3840;
            #pragma unroll
            for (int k = 0; k < 8; k++) {
                int id = tid + k * 512;
                if (id < 3840) pf[k] = gw[id];
            }
        }
        #pragma unroll
        for (int ciL = 0; ciL < 2; ciL++) {
            int ci = st * 2 + ciL;
            const unsigned long long* wp = wb + ciL * 1920 + co * 30;
            const ulonglong2* wp2 = (const ulonglong2*)wp;
            const float* bA = xa + ci * 144;
            const float* bB = xb + ci * 144;
            unsigned long long wprev[5];
            #pragma unroll
            for (int ir = 0; ir < 6; ir++) {
                ulonglong2 eA0 = *(const ulonglong2*)(bA + ir * 12);
                ulonglong2 eA1 = *(const ulonglong2*)(bA + ir * 12 + 4);
                ulonglong2 eA2 = *(const ulonglong2*)(bA + ir * 12 + 8);
                ulonglong2 eB0 = *(const ulonglong2*)(bB + ir * 12);
                ulonglong2 eB1 = *(const ulonglong2*)(bB + ir * 12 + 4);
                unsigned long long eB2 = *(const unsigned long long*)(bB + ir * 12 + 8);
                unsigned long long pe[6] = {eA0.x, eA0.y, eA1.x, eA1.y, eA2.x, eA2.y};
                unsigned long long po[5] = {eB0.x, eB0.y, eB1.x, eB1.y, eB2};
                unsigned long long wcur[5];
                if (ir <= 4) {
                    // padded ky-row: 2x LDS.128 + 1x LDS.64
                    ulonglong2 qa = wp2[ir * 3];
                    ulonglong2 qb = wp2[ir * 3 + 1];
                    wcur[0] = qa.x; wcur[1] = qa.y;
                    wcur[2] = qb.x; wcur[3] = qb.y;
                    wcur[4] = wp[ir * 6 + 4];
                    #pragma unroll
                    for (int kx = 0; kx < 5; kx++) {
                        int h = kx >> 1;
                        const unsigned long long* src = (kx & 1) ? po : pe;
                        fma2(a0[0], src[h + 0], wcur[kx]);
                        fma2(a0[1], src[h + 1], wcur[kx]);
                        fma2(a0[2], src[h + 2], wcur[kx]);
                        fma2(a0[3], src[h + 3], wcur[kx]);
                    }
                }
                if (ir >= 1) {
                    #pragma unroll
                    for (int kx = 0; kx < 5; kx++) {
                        int h = kx >> 1;
                        const unsigned long long* src = (kx & 1) ? po : pe;
                        fma2(a1[0], src[h + 0], wprev[kx]);
                        fma2(a1[1], src[h + 1], wprev[kx]);
                        fma2(a1[2], src[h + 2], wprev[kx]);
                        fma2(a1[3], src[h + 3], wprev[kx]);
                    }
                }
                #pragma unroll
                for (int kx = 0; kx < 5; kx++) wprev[kx] = wcur[kx];
            }
        }
    }

    // epilogue: 2x2 pool + relu entirely in-thread
    #pragma unroll
    for (int j = 0; j < 4; j++) {
        float r0lo, r0hi, r1lo, r1hi;
        upk2(a0[j], r0lo, r0hi);
        upk2(a1[j], r1lo, r1hi);
        float p = fmaxf(fmaxf(r0lo, r0hi), fmaxf(r1lo, r1hi));
        p = fmaxf(p, 0.0f);
        int fb = co * 16 + q * 4 + j;
        g_h2[(n0 + s) * 1024 + fb] = p;
        atomicAdd(&g_stat3[fb], p * (1.0f / 2048.0f));
    }
}

// ---------------- kernel 6: linear effective params --------------------------
__global__ void wl_kernel(const float* __restrict__ w0, const float* __restrict__ wS2,
                          const float* __restrict__ wG, const float* __restrict__ weta,
                          const float* __restrict__ wM, const float* __restrict__ b0,
                          const float* __restrict__ bS2, const float* __restrict__ bG,
                          const float* __restrict__ beta) {
    int idx = blockIdx.x * 256 + threadIdx.x;
    if (idx < 10240) {
        int i = idx & 1023;
        float M = fmaxf(wM[idx], g_stat3[i]);
        // NOTE: linear weight cond is wS2 != 0 (not wG), per reference
        g_wl[idx] = scinol(w0[idx], wS2[idx], wG[idx], weta[idx], M, wS2[idx] != 0.0f);
    } else if (idx < 10250) {
        int j = idx - 10240;
        g_bl[j] = scinol(b0[j], bS2[j], bG[j], beta[j], 1.0f, bS2[j] != 0.0f);
    }
}

// ---------------- kernel 7: linear layer -------------------------------------
__global__ void __launch_bounds__(256) linear_kernel(float* __restrict__ out) {
    __shared__ float w_s[10240];
    __shared__ float b_s[16];
    for (int i = threadIdx.x; i < 10240; i += 256) w_s[i] = g_wl[i];
    if (threadIdx.x < 10) b_s[threadIdx.x] = g_bl[threadIdx.x];
    __syncthreads();
    int warp = threadIdx.x >> 5, lane = threadIdx.x & 31;
    for (int n = blockIdx.x * 8 + warp; n < 2048; n += 64 * 8) {
        const float* h = g_h2 + n * 1024;
        float hv[32];
        #pragma unroll
        for (int j = 0; j < 32; j++) hv[j] = h[lane + j * 32];
        #pragma unroll 1
        for (int o = 0; o < 10; o++) {
            float s = 0.0f;
            #pragma unroll
            for (int j = 0; j < 32; j++) s = fmaf(hv[j], w_s[o * 1024 + lane + j * 32], s);
            #pragma unroll
            for (int off = 16; off; off >>= 1) s += __shfl_xor_sync(0xffffffffu, s, off);
            if (lane == 0) out[n * 10 + o] = s + b_s[o];
        }
    }
}

// ---------------- launch ------------------------------------------------------
extern "C" void kernel_launch(void* const* d_in, const int* in_sizes, int n_in,
                              void* d_out, int out_size) {
    const float* x = (const float*)d_in[0];
    const float* c1[9]; for (int i = 0; i < 9; i++) c1[i] = (const float*)d_in[1 + i];
    const float* c2[9]; for (int i = 0; i < 9; i++) c2[i] = (const float*)d_in[10 + i];
    const float* lp[9]; for (int i = 0; i < 9; i++) lp[i] = (const float*)d_in[19 + i];
    float* out = (float*)d_out;

    // xsA + xsB (2 samples each) + double-buffered 2-ci padded weight ring
    const int conv2_smem = 36864 * 4 + 2 * 3840 * 8;  // 208896 B
    cudaFuncSetAttribute(conv2_kernel, cudaFuncAttributeMaxDynamicSharedMemorySize,
                         conv2_smem);

    zero_stats_kernel<<<1, 1024>>>();
    stat1_kernel<<<2048, 256>>>(x);
    w1_kernel<<<7, 256>>>(c1[0], c1[1], c1[2], c1[3], c1[4], c1[5], c1[6], c1[7], c1[8]);
    conv1_kernel<<<2048, 256>>>(x);
    w2_kernel<<<481, 256>>>(c2[0], c2[1], c2[2], c2[3], c2[4], c2[5], c2[6], c2[7], c2[8]);
    conv2_kernel<<<1024, 512, conv2_smem>>>();
    wl_kernel<<<41, 256>>>(lp[0], lp[1], lp[2], lp[3], lp[4], lp[5], lp[6], lp[7], lp[8]);
    linear_kernel<<<64, 256>>>(out);
}

// round 10
// speedup vs baseline: 1.0109x; 1.0053x over previous
#include <cuda_runtime.h>

// ---------------- device scratch (allocation-free: __device__ globals) -------
__device__ float g_stat1;            // conv1 input stat (scalar, C_in=1)
__device__ float g_stat2[64];        // conv2 input stat per channel
__device__ float g_stat3[1024];      // linear input stat per feature
__device__ float g_w1[1600];         // conv1 effective weights (64,1,5,5)
__device__ float g_b1[64];
// conv2 eff weights, splatted (w,w) pairs, ky-rows padded to 6:
// idx = ((ci*64 + co)*5 + ky)*6 + kx, kx<5 valid, kx=5 zero pad
__device__ unsigned long long g_w2r[64 * 64 * 5 * 6];
__device__ float g_b2[64];
__device__ float g_wl[10240];        // linear eff weights (10,1024)
__device__ float g_bl[10];
__device__ __align__(16) float g_h1[2048 * 64 * 144]; // pooled conv1 out (N,64,12,12)
__device__ __align__(16) float g_h2[2048 * 1024];     // pooled conv2 out (N,1024)

// ---------------- helpers ----------------------------------------------------
__device__ __forceinline__ float scinol(float p0, float S2, float G, float eta,
                                        float M, bool cond) {
    float denom = sqrtf(S2 + M * M);
    float theta = fminf(fmaxf(G / denom, -1.0f), 1.0f);
    float upd = cond ? theta / (2.0f * denom) * eta : 0.0f;
    return p0 + upd;
}

__device__ __forceinline__ unsigned long long pk2(float v) {
    unsigned long long r;
    asm("mov.b64 %0, {%1, %2};" : "=l"(r) : "f"(v), "f"(v));
    return r;
}
__device__ __forceinline__ void fma2(unsigned long long& d, unsigned long long a,
                                     unsigned long long b) {
    asm("fma.rn.f32x2 %0, %1, %2, %0;" : "+l"(d) : "l"(a), "l"(b));
}
__device__ __forceinline__ void upk2(unsigned long long v, float& lo, float& hi) {
    asm("mov.b64 {%0, %1}, %2;" : "=f"(lo), "=f"(hi) : "l"(v));
}

// ---------------- kernel 0: zero stat accumulators ---------------------------
__global__ void zero_stats_kernel() {
    int i = threadIdx.x;
    if (i == 0) g_stat1 = 0.0f;
    if (i < 64) g_stat2[i] = 0.0f;
    if (i < 1024) g_stat3[i] = 0.0f;
}

// ---------------- kernel 1: stat1 = mean_n max_hw |x| ------------------------
__global__ void stat1_kernel(const float* __restrict__ x) {
    int n = blockIdx.x;
    const float* xs = x + n * 784;
    float m = 0.0f;
    for (int i = threadIdx.x; i < 784; i += 256) m = fmaxf(m, fabsf(xs[i]));
    __shared__ float red[8];
    #pragma unroll
    for (int o = 16; o; o >>= 1) m = fmaxf(m, __shfl_xor_sync(0xffffffffu, m, o));
    if ((threadIdx.x & 31) == 0) red[threadIdx.x >> 5] = m;
    __syncthreads();
    if (threadIdx.x < 8) {
        m = red[threadIdx.x];
        #pragma unroll
        for (int o = 4; o; o >>= 1) m = fmaxf(m, __shfl_xor_sync(0x000000ffu, m, o));
        if (threadIdx.x == 0) atomicAdd(&g_stat1, m * (1.0f / 2048.0f));
    }
}

// ---------------- kernel 2: conv1 effective params ---------------------------
__global__ void w1_kernel(const float* __restrict__ w0, const float* __restrict__ wS2,
                          const float* __restrict__ wG, const float* __restrict__ weta,
                          const float* __restrict__ wM, const float* __restrict__ b0,
                          const float* __restrict__ bS2, const float* __restrict__ bG,
                          const float* __restrict__ beta) {
    int i = blockIdx.x * 256 + threadIdx.x;
    if (i < 1600) {
        float M = fmaxf(g_stat1, wM[0]);  // C_in = 1
        g_w1[i] = scinol(w0[i], wS2[i], wG[i], weta[i], M, wG[i] != 0.0f);
    } else if (i < 1664) {
        int j = i - 1600;
        g_b1[j] = scinol(b0[j], bS2[j], bG[j], beta[j], 1.0f, bG[j] != 0.0f);
    }
}

// ---------------- kernel 3: conv1 + relu + pool + stat2 (f32x2, broadcast) ---
// 1536 half-tasks per sample: task = (py, half, c); lanes differ in c only ->
// x LDS.64 loads are warp-broadcast. Each task: 2 conv rows x 12 cols packed.
// NOTE: xb (shift-1 copy) fill is SINGLE-WRITER (r4 had a write race here).
__global__ void __launch_bounds__(256) conv1_kernel(const float* __restrict__ x) {
    __shared__ float xs[788];
    __shared__ float xb[788];                 // shift-1 copy
    __shared__ unsigned long long wsp[1600];  // splatted (w,w) pairs
    __shared__ float bs[64];
    __shared__ unsigned int smax[64];
    int n = blockIdx.x;
    int tid = threadIdx.x;
    const float* xp = x + n * 784;
    for (int i = tid; i < 784; i += 256) {
        xs[i] = xp[i];
        xb[i] = (i < 783) ? xp[i + 1] : 0.0f;   // single writer per slot
    }
    for (int i = tid; i < 1600; i += 256) wsp[i] = pk2(g_w1[i]);
    if (tid < 64) { bs[tid] = g_b1[tid]; smax[tid] = 0u; }
    __syncthreads();

    #pragma unroll 1
    for (int it = 0; it < 6; it++) {
        int task = it * 256 + tid;           // 1536 tasks
        int c = task & 63;
        int r2i = task >> 6;                 // 0..23
        int py = r2i >> 1;                   // pooled row 0..11
        int hf = r2i & 1;                    // column half
        int base0 = 2 * py * 28 + hf * 12;

        unsigned long long A0[6], A1[6];
        {
            unsigned long long bi = pk2(bs[c]);
            #pragma unroll
            for (int j = 0; j < 6; j++) { A0[j] = bi; A1[j] = bi; }
        }
        const unsigned long long* wc = wsp + c * 25;
        unsigned long long wprev[5];
        #pragma unroll
        for (int i6 = 0; i6 < 6; i6++) {
            int base = base0 + i6 * 28;
            unsigned long long pe[8], po[7];
            #pragma unroll
            for (int k = 0; k < 8; k++)
                pe[k] = *(const unsigned long long*)(xs + base + 2 * k);
            #pragma unroll
            for (int k = 0; k < 7; k++)
                po[k] = *(const unsigned long long*)(xb + base + 2 * k);
            unsigned long long wcur[5];
            if (i6 <= 4) {
                #pragma unroll
                for (int kx = 0; kx < 5; kx++) wcur[kx] = wc[i6 * 5 + kx];
                #pragma unroll
                for (int kx = 0; kx < 5; kx++) {
                    const unsigned long long* src =
                        (kx & 1) ? (po + ((kx - 1) >> 1)) : (pe + (kx >> 1));
                    #pragma unroll
                    for (int j = 0; j < 6; j++) fma2(A0[j], src[j], wcur[kx]);
                }
            }
            if (i6 >= 1) {
                #pragma unroll
                for (int kx = 0; kx < 5; kx++) {
                    const unsigned long long* src =
                        (kx & 1) ? (po + ((kx - 1) >> 1)) : (pe + (kx >> 1));
                    #pragma unroll
                    for (int j = 0; j < 6; j++) fma2(A1[j], src[j], wprev[kx]);
                }
            }
            #pragma unroll
            for (int kx = 0; kx < 5; kx++) wprev[kx] = wcur[kx];
        }
        float rmax = 0.0f;
        float* hp = g_h1 + n * 9216 + c * 144 + py * 12 + hf * 6;
        #pragma unroll
        for (int j = 0; j < 6; j++) {
            float a, b, cc, d;
            upk2(A0[j], a, b);
            upk2(A1[j], cc, d);
            float v = fmaxf(fmaxf(a, b), fmaxf(cc, d));
            v = fmaxf(v, 0.0f);              // relu-then-pool == pool-then-relu
            hp[j] = v;
            rmax = fmaxf(rmax, v);
        }
        atomicMax(&smax[c], __float_as_uint(rmax));  // vals >= 0
    }
    __syncthreads();
    if (tid < 64)
        atomicAdd(&g_stat2[tid], __uint_as_float(smax[tid]) * (1.0f / 2048.0f));
}

// ---------------- kernel 4: conv2 effective params (padded ky-row pairs) -----
__global__ void w2_kernel(const float* __restrict__ w0, const float* __restrict__ wS2,
                          const float* __restrict__ wG, const float* __restrict__ weta,
                          const float* __restrict__ wM, const float* __restrict__ b0,
                          const float* __restrict__ bS2, const float* __restrict__ bG,
                          const float* __restrict__ beta) {
    int idx = blockIdx.x * 256 + threadIdx.x;
    const int NW = 64 * 64 * 5 * 6;   // 122880
    if (idx < NW) {
        int kx = idx % 6;
        int t = idx / 6;
        int ky = t % 5;
        int t2 = t / 5;          // ci*64 + co
        int co = t2 & 63;
        int ci = t2 >> 6;
        float v = 0.0f;
        if (kx < 5) {
            int src = co * 1600 + ci * 25 + ky * 5 + kx;
            float M = fmaxf(g_stat2[ci], wM[ci]);
            v = scinol(w0[src], wS2[src], wG[src], weta[src], M, wG[src] != 0.0f);
        }
        float2 p; p.x = v; p.y = v;
        ((float2*)g_w2r)[idx] = p;
    } else if (idx < NW + 64) {
        int j = idx - NW;
        g_b2[j] = scinol(b0[j], bS2[j], bG[j], beta[j], 1.0f, bG[j] != 0.0f);
    }
}

// ---------------- kernel 5: conv2 + relu + pool + stat3 ----------------------
// CTA = 2 samples, 512 threads (16 warps). warp = (sample, row-pair q, co-half);
// lane = co. x loads warp-broadcast; weights as padded 6-pair ky-rows -> each
// 5-pair row loads as 2x LDS.128 + 1x LDS.64, streamed wcur/wprev, from a
// double-buffered 2-ci smem ring prefetched through registers.
extern __shared__ float cs2[];
__global__ void __launch_bounds__(512) conv2_kernel() {
    float* xsA = cs2;                                   // 2*9216 floats
    float* xsB = cs2 + 18432;                           // 2*9216 floats (shift-1)
    unsigned long long* wring = (unsigned long long*)(cs2 + 36864);  // 2*3840 ull
    int tid = threadIdx.x;
    int n0 = blockIdx.x * 2;

    #pragma unroll
    for (int sl = 0; sl < 2; sl++) {
        const float* h1 = g_h1 + (n0 + sl) * 9216;
        float* xa = xsA + sl * 9216;
        float* xb = xsB + sl * 9216;
        for (int i = tid; i < 2304; i += 512)
            ((float4*)xa)[i] = ((const float4*)h1)[i];
        for (int i = tid; i < 9216; i += 512)
            xb[i] = (i < 9215) ? h1[i + 1] : 0.0f;
    }

    int w = tid >> 5, lane = tid & 31;
    int s = w >> 3;            // sample within CTA
    int q = (w >> 1) & 3;      // pooled row pair: conv rows 2q, 2q+1
    int co = (w & 1) * 32 + lane;

    const float* xa = xsA + s * 9216 + q * 24;
    const float* xb = xsB + s * 9216 + q * 24;

    unsigned long long a0[4], a1[4];
    {
        unsigned long long bi = pk2(g_b2[co]);
        #pragma unroll
        for (int j = 0; j < 4; j++) { a0[j] = bi; a1[j] = bi; }
    }

    // prologue: stage-0 (2 ci) weight pairs into registers
    unsigned long long pf[8];
    #pragma unroll
    for (int k = 0; k < 8; k++) {
        int id = tid + k * 512;
        if (id < 3840) pf[k] = g_w2r[id];
    }

    #pragma unroll 1
    for (int st = 0; st < 32; st++) {
        unsigned long long* wb = wring + (st & 1) * 3840;
        #pragma unroll
        for (int k = 0; k < 8; k++) {
            int id = tid + k * 512;
            if (id < 3840) wb[id] = pf[k];
        }
        __syncthreads();
        if (st < 31) {
            const unsigned long long* gw = g_w2r + (st + 1) * 3840;
            #pragma unroll
            for (int k = 0; k < 8; k++) {
                int id = tid + k * 512;
                if (id < 3840) pf[k] = gw[id];
            }
        }
        #pragma unroll
        for (int ciL = 0; ciL < 2; ciL++) {
            int ci = st * 2 + ciL;
            const unsigned long long* wp = wb + ciL * 1920 + co * 30;
            const ulonglong2* wp2 = (const ulonglong2*)wp;
            const float* bA = xa + ci * 144;
            const float* bB = xb + ci * 144;
            unsigned long long wprev[5];
            #pragma unroll
            for (int ir = 0; ir < 6; ir++) {
                ulonglong2 eA0 = *(const ulonglong2*)(bA + ir * 12);
                ulonglong2 eA1 = *(const ulonglong2*)(bA + ir * 12 + 4);
                ulonglong2 eA2 = *(const ulonglong2*)(bA + ir * 12 + 8);
                ulonglong2 eB0 = *(const ulonglong2*)(bB + ir * 12);
                ulonglong2 eB1 = *(const ulonglong2*)(bB + ir * 12 + 4);
                unsigned long long eB2 = *(const unsigned long long*)(bB + ir * 12 + 8);
                unsigned long long pe[6] = {eA0.x, eA0.y, eA1.x, eA1.y, eA2.x, eA2.y};
                unsigned long long po[5] = {eB0.x, eB0.y, eB1.x, eB1.y, eB2};
                unsigned long long wcur[5];
                if (ir <= 4) {
                    // padded ky-row: 2x LDS.128 + 1x LDS.64
                    ulonglong2 qa = wp2[ir * 3];
                    ulonglong2 qb = wp2[ir * 3 + 1];
                    wcur[0] = qa.x; wcur[1] = qa.y;
                    wcur[2] = qb.x; wcur[3] = qb.y;
                    wcur[4] = wp[ir * 6 + 4];
                    #pragma unroll
                    for (int kx = 0; kx < 5; kx++) {
                        int h = kx >> 1;
                        const unsigned long long* src = (kx & 1) ? po : pe;
                        fma2(a0[0], src[h + 0], wcur[kx]);
                        fma2(a0[1], src[h + 1], wcur[kx]);
                        fma2(a0[2], src[h + 2], wcur[kx]);
                        fma2(a0[3], src[h + 3], wcur[kx]);
                    }
                }
                if (ir >= 1) {
                    #pragma unroll
                    for (int kx = 0; kx < 5; kx++) {
                        int h = kx >> 1;
                        const unsigned long long* src = (kx & 1) ? po : pe;
                        fma2(a1[0], src[h + 0], wprev[kx]);
                        fma2(a1[1], src[h + 1], wprev[kx]);
                        fma2(a1[2], src[h + 2], wprev[kx]);
                        fma2(a1[3], src[h + 3], wprev[kx]);
                    }
                }
                #pragma unroll
                for (int kx = 0; kx < 5; kx++) wprev[kx] = wcur[kx];
            }
        }
    }

    // epilogue: 2x2 pool + relu entirely in-thread
    #pragma unroll
    for (int j = 0; j < 4; j++) {
        float r0lo, r0hi, r1lo, r1hi;
        upk2(a0[j], r0lo, r0hi);
        upk2(a1[j], r1lo, r1hi);
        float p = fmaxf(fmaxf(r0lo, r0hi), fmaxf(r1lo, r1hi));
        p = fmaxf(p, 0.0f);
        int fb = co * 16 + q * 4 + j;
        g_h2[(n0 + s) * 1024 + fb] = p;
        atomicAdd(&g_stat3[fb], p * (1.0f / 2048.0f));
    }
}

// ---------------- kernel 6: linear effective params --------------------------
__global__ void wl_kernel(const float* __restrict__ w0, const float* __restrict__ wS2,
                          const float* __restrict__ wG, const float* __restrict__ weta,
                          const float* __restrict__ wM, const float* __restrict__ b0,
                          const float* __restrict__ bS2, const float* __restrict__ bG,
                          const float* __restrict__ beta) {
    int idx = blockIdx.x * 256 + threadIdx.x;
    if (idx < 10240) {
        int i = idx & 1023;
        float M = fmaxf(wM[idx], g_stat3[i]);
        // NOTE: linear weight cond is wS2 != 0 (not wG), per reference
        g_wl[idx] = scinol(w0[idx], wS2[idx], wG[idx], weta[idx], M, wS2[idx] != 0.0f);
    } else if (idx < 10250) {
        int j = idx - 10240;
        g_bl[j] = scinol(b0[j], bS2[j], bG[j], beta[j], 1.0f, bS2[j] != 0.0f);
    }
}

// ---------------- kernel 7: linear layer -------------------------------------
__global__ void __launch_bounds__(256) linear_kernel(float* __restrict__ out) {
    __shared__ float w_s[10240];
    __shared__ float b_s[16];
    for (int i = threadIdx.x; i < 10240; i += 256) w_s[i] = g_wl[i];
    if (threadIdx.x < 10) b_s[threadIdx.x] = g_bl[threadIdx.x];
    __syncthreads();
    int warp = threadIdx.x >> 5, lane = threadIdx.x & 31;
    for (int n = blockIdx.x * 8 + warp; n < 2048; n += 64 * 8) {
        const float* h = g_h2 + n * 1024;
        float hv[32];
        #pragma unroll
        for (int j = 0; j < 32; j++) hv[j] = h[lane + j * 32];
        #pragma unroll 1
        for (int o = 0; o < 10; o++) {
            float s = 0.0f;
            #pragma unroll
            for (int j = 0; j < 32; j++) s = fmaf(hv[j], w_s[o * 1024 + lane + j * 32], s);
            #pragma unroll
            for (int off = 16; off; off >>= 1) s += __shfl_xor_sync(0xffffffffu, s, off);
            if (lane == 0) out[n * 10 + o] = s + b_s[o];
        }
    }
}

// ---------------- launch ------------------------------------------------------
extern "C" void kernel_launch(void* const* d_in, const int* in_sizes, int n_in,
                              void* d_out, int out_size) {
    const float* x = (const float*)d_in[0];
    const float* c1[9]; for (int i = 0; i < 9; i++) c1[i] = (const float*)d_in[1 + i];
    const float* c2[9]; for (int i = 0; i < 9; i++) c2[i] = (const float*)d_in[10 + i];
    const float* lp[9]; for (int i = 0; i < 9; i++) lp[i] = (const float*)d_in[19 + i];
    float* out = (float*)d_out;

    // xsA + xsB (2 samples each) + double-buffered 2-ci padded weight ring
    const int conv2_smem = 36864 * 4 + 2 * 3840 * 8;  // 208896 B
    cudaFuncSetAttribute(conv2_kernel, cudaFuncAttributeMaxDynamicSharedMemorySize,
                         conv2_smem);

    zero_stats_kernel<<<1, 1024>>>();
    stat1_kernel<<<2048, 256>>>(x);
    w1_kernel<<<7, 256>>>(c1[0], c1[1], c1[2], c1[3], c1[4], c1[5], c1[6], c1[7], c1[8]);
    conv1_kernel<<<2048, 256>>>(x);
    w2_kernel<<<481, 256>>>(c2[0], c2[1], c2[2], c2[3], c2[4], c2[5], c2[6], c2[7], c2[8]);
    conv2_kernel<<<1024, 512, conv2_smem>>>();
    wl_kernel<<<41, 256>>>(lp[0], lp[1], lp[2], lp[3], lp[4], lp[5], lp[6], lp[7], lp[8]);
    linear_kernel<<<64, 256>>>(out);
}

// round 13
// speedup vs baseline: 2.3670x; 2.3415x over previous
#include <cuda_runtime.h>
#include <cuda_bf16.h>
#include <stdint.h>

// ======================= device scratch (no allocs) ==========================
__device__ float g_stat1;
__device__ float g_stat2[64];
__device__ float g_stat3[1024];
__device__ float g_w1[1600];
__device__ float g_b1[64];
__device__ float g_b2[64];
__device__ float g_wl[10240];
__device__ float g_bl[10];
// conv1 out, transposed+packed: u32 = (bf16_lo<<16)|bf16_hi, [n][yx=144][ci=64]
__device__ __align__(16) unsigned g_h1hl[2048 * 9216];
// conv2 weights in mma B-fragment layout: u64[(t*2+split)*1024 + nt*128 + k*32 + lane]
// u64 = {b0 = bf16x2 (ci0,ci0+1), b1 = bf16x2 (ci0+8,ci0+9)}, ci0 = k*16+(lane&3)*2,
// co = nt*8 + (lane>>2). split 0 = w_hi, 1 = w_lo.
__device__ __align__(16) unsigned long long g_w2f[25 * 2 * 1024];
__device__ __align__(16) float g_h2[2048 * 1024];

// ======================= helpers =============================================
__device__ __forceinline__ float scinol(float p0, float S2, float G, float eta,
                                        float M, bool cond) {
    float denom = sqrtf(S2 + M * M);
    float theta = fminf(fmaxf(G / denom, -1.0f), 1.0f);
    float upd = cond ? theta / (2.0f * denom) * eta : 0.0f;
    return p0 + upd;
}

#define MMA_BF16(c, a, b0r, b1r) \
    asm volatile("mma.sync.aligned.m16n8k16.row.col.f32.bf16.bf16.f32 " \
        "{%0,%1,%2,%3}, {%4,%5,%6,%7}, {%8,%9}, {%0,%1,%2,%3};" \
        : "+f"((c)[0]), "+f"((c)[1]), "+f"((c)[2]), "+f"((c)[3]) \
        : "r"((a)[0]), "r"((a)[1]), "r"((a)[2]), "r"((a)[3]), "r"(b0r), "r"(b1r))

// ======================= kernel 0: zero stats ================================
__global__ void zero_stats_kernel() {
    int i = threadIdx.x;
    if (i == 0) g_stat1 = 0.0f;
    if (i < 64) g_stat2[i] = 0.0f;
    if (i < 1024) g_stat3[i] = 0.0f;
}

// ======================= kernel 1: stat1 =====================================
__global__ void stat1_kernel(const float* __restrict__ x) {
    int n = blockIdx.x;
    const float* xs = x + n * 784;
    float m = 0.0f;
    for (int i = threadIdx.x; i < 784; i += 256) m = fmaxf(m, fabsf(xs[i]));
    __shared__ float red[8];
    #pragma unroll
    for (int o = 16; o; o >>= 1) m = fmaxf(m, __shfl_xor_sync(0xffffffffu, m, o));
    if ((threadIdx.x & 31) == 0) red[threadIdx.x >> 5] = m;
    __syncthreads();
    if (threadIdx.x < 8) {
        m = red[threadIdx.x];
        #pragma unroll
        for (int o = 4; o; o >>= 1) m = fmaxf(m, __shfl_xor_sync(0x000000ffu, m, o));
        if (threadIdx.x == 0) atomicAdd(&g_stat1, m * (1.0f / 2048.0f));
    }
}

// ======================= kernel 2: conv1 params ==============================
__global__ void w1_kernel(const float* __restrict__ w0, const float* __restrict__ wS2,
                          const float* __restrict__ wG, const float* __restrict__ weta,
                          const float* __restrict__ wM, const float* __restrict__ b0,
                          const float* __restrict__ bS2, const float* __restrict__ bG,
                          const float* __restrict__ beta) {
    int i = blockIdx.x * 256 + threadIdx.x;
    if (i < 1600) {
        float M = fmaxf(g_stat1, wM[0]);
        g_w1[i] = scinol(w0[i], wS2[i], wG[i], weta[i], M, wG[i] != 0.0f);
    } else if (i < 1664) {
        int j = i - 1600;
        g_b1[j] = scinol(b0[j], bS2[j], bG[j], beta[j], 1.0f, bG[j] != 0.0f);
    }
}

// ======================= kernel 3: conv1 (proven r2 body) + pack =============
__global__ void __launch_bounds__(256) conv1_kernel(const float* __restrict__ x) {
    __shared__ float xs[784];
    __shared__ float ws[1600];
    __shared__ float bs[64];
    __shared__ unsigned smax[64];
    __shared__ float hbuf[64 * 145];
    int n = blockIdx.x;
    int tid = threadIdx.x;
    const float* xp = x + n * 784;
    for (int i = tid; i < 784; i += 256) xs[i] = xp[i];
    for (int i = tid; i < 1600; i += 256) ws[i] = g_w1[i];
    if (tid < 64) { bs[tid] = g_b1[tid]; smax[tid] = 0u; }
    __syncthreads();

    #pragma unroll 1
    for (int it = 0; it < 3; it++) {
        int task = tid + it * 256;           // 768 = 64ch x 12 pooled rows
        int c = task / 12;
        int py = task % 12;
        float a0[24], a1[24];
        float b = bs[c];
        #pragma unroll
        for (int j = 0; j < 24; j++) { a0[j] = b; a1[j] = b; }
        const float* wc = ws + c * 25;
        #pragma unroll
        for (int i6 = 0; i6 < 6; i6++) {
            int iy = 2 * py + i6;
            float4 xq[7];
            const float4* rp = (const float4*)(xs + iy * 28);
            #pragma unroll
            for (int j = 0; j < 7; j++) xq[j] = rp[j];
            const float* xr = (const float*)xq;
            if (i6 <= 4) {
                #pragma unroll
                for (int kx = 0; kx < 5; kx++) {
                    float w = wc[i6 * 5 + kx];
                    #pragma unroll
                    for (int ox = 0; ox < 24; ox++) a0[ox] = fmaf(xr[ox + kx], w, a0[ox]);
                }
            }
            if (i6 >= 1) {
                #pragma unroll
                for (int kx = 0; kx < 5; kx++) {
                    float w = wc[(i6 - 1) * 5 + kx];
                    #pragma unroll
                    for (int ox = 0; ox < 24; ox++) a1[ox] = fmaf(xr[ox + kx], w, a1[ox]);
                }
            }
        }
        float rmax = 0.0f;
        float* hp = hbuf + c * 145 + py * 12;
        #pragma unroll
        for (int px = 0; px < 12; px++) {
            float v = fmaxf(fmaxf(a0[2 * px], a0[2 * px + 1]),
                            fmaxf(a1[2 * px], a1[2 * px + 1]));
            v = fmaxf(v, 0.0f);
            hp[px] = v;
            rmax = fmaxf(rmax, v);
        }
        atomicMax(&smax[c], __float_as_uint(rmax));
    }
    __syncthreads();
    if (tid < 64)
        atomicAdd(&g_stat2[tid], __uint_as_float(smax[tid]) * (1.0f / 2048.0f));

    // transpose + bf16 hi/lo pack -> g_h1hl[n][yx][ci]
    unsigned* dst = g_h1hl + n * 9216;
    #pragma unroll 1
    for (int j = tid; j < 288; j += 256) {
        int yx = j >> 1;
        int c0 = (j & 1) * 32;
        unsigned ow[32];
        #pragma unroll
        for (int k = 0; k < 32; k++) {
            float v = hbuf[(c0 + k) * 145 + yx];
            __nv_bfloat16 h = __float2bfloat16(v);
            float lf = v - __bfloat162float(h);
            __nv_bfloat16 l = __float2bfloat16(lf);
            ow[k] = ((unsigned)__bfloat16_as_ushort(l) << 16) |
                    (unsigned)__bfloat16_as_ushort(h);
        }
        uint4* dq = (uint4*)(dst + yx * 64 + c0);
        #pragma unroll
        for (int k = 0; k < 8; k++)
            dq[k] = make_uint4(ow[4 * k], ow[4 * k + 1], ow[4 * k + 2], ow[4 * k + 3]);
    }
}

// ======================= kernel 4: conv2 params -> B-fragment layout =========
__global__ void w2_kernel(const float* __restrict__ w0, const float* __restrict__ wS2,
                          const float* __restrict__ wG, const float* __restrict__ weta,
                          const float* __restrict__ wM, const float* __restrict__ b0,
                          const float* __restrict__ bS2, const float* __restrict__ bG,
                          const float* __restrict__ beta) {
    int idx = blockIdx.x * 256 + threadIdx.x;
    if (idx < 102400) {          // co*1600 + ci*25 + t
        int co = idx / 1600;
        int rem = idx % 1600;
        int ci = rem / 25;
        int t = rem % 25;
        float M = fmaxf(g_stat2[ci], wM[ci]);
        float v = scinol(w0[idx], wS2[idx], wG[idx], weta[idx], M, wG[idx] != 0.0f);
        __nv_bfloat16 h = __float2bfloat16(v);
        float lf = v - __bfloat162float(h);
        __nv_bfloat16 l = __float2bfloat16(lf);
        int k = ci >> 4, cil = ci & 15;
        int bsel = cil >> 3, pairpos = (cil >> 1) & 3, half = cil & 1;
        int lane = (co & 7) * 4 + pairpos;
        int nt = co >> 3;
        unsigned short* w16 = (unsigned short*)g_w2f;
        long base = ((long)(t * 2) * 1024 + nt * 128 + k * 32 + lane) * 4 + bsel * 2 + half;
        w16[base] = __bfloat16_as_ushort(h);
        w16[base + 4096] = __bfloat16_as_ushort(l);   // split-1 table is +1024 u64
    } else if (idx < 102464) {
        int j = idx - 102400;
        g_b2[j] = scinol(b0[j], bS2[j], bG[j], beta[j], 1.0f, bG[j] != 0.0f);
    }
}

// ======================= kernel 5: conv2 via mma.sync bf16 ===================
// CTA = 2 samples, 128 thr (4 warps). Warp w: rows w*32..w*32+31 of
// D[128 = 2x(8y x 8x), 64 co]; acc = 2 mtiles x 8 ntiles x 4 f32.
// X staged as two bf16 planes (hi/lo), 288 rows x 72 bf16 (stride 36 u32):
// A-frag LDS.32 banks = 4*(lane>>2) + (lane&3) -> conflict-free.
// W staged per shift (16KB frag layout) via register-prefetched ring.
#define XH_OFF 0
#define XL_OFF 10368
#define WF_OFF 20736          // u32 offset; 2048 u64
#define C2_SMEM ((20736 + 4096) * 4)

extern __shared__ unsigned c2s[];
__global__ void __launch_bounds__(128) conv2_mma_kernel() {
    int tid = threadIdx.x, lane = tid & 31, w = tid >> 5;
    int n0 = blockIdx.x * 2;
    unsigned* Xh = c2s + XH_OFF;
    unsigned long long* Wf = (unsigned long long*)(c2s + WF_OFF);

    // stage X planes: 288 rows x 4 quarters(16 ci)
    #pragma unroll 1
    for (int j = tid; j < 1152; j += 128) {
        int row = j >> 2, q = j & 3;
        const uint4* src = (const uint4*)(g_h1hl + n0 * 9216 + row * 64 + q * 16);
        uint4 x0 = src[0], x1 = src[1], x2 = src[2], x3 = src[3];
        unsigned hh[8], ll[8];
        hh[0] = __byte_perm(x0.x, x0.y, 0x5410); ll[0] = __byte_perm(x0.x, x0.y, 0x7632);
        hh[1] = __byte_perm(x0.z, x0.w, 0x5410); ll[1] = __byte_perm(x0.z, x0.w, 0x7632);
        hh[2] = __byte_perm(x1.x, x1.y, 0x5410); ll[2] = __byte_perm(x1.x, x1.y, 0x7632);
        hh[3] = __byte_perm(x1.z, x1.w, 0x5410); ll[3] = __byte_perm(x1.z, x1.w, 0x7632);
        hh[4] = __byte_perm(x2.x, x2.y, 0x5410); ll[4] = __byte_perm(x2.x, x2.y, 0x7632);
        hh[5] = __byte_perm(x2.z, x2.w, 0x5410); ll[5] = __byte_perm(x2.z, x2.w, 0x7632);
        hh[6] = __byte_perm(x3.x, x3.y, 0x5410); ll[6] = __byte_perm(x3.x, x3.y, 0x7632);
        hh[7] = __byte_perm(x3.z, x3.w, 0x5410); ll[7] = __byte_perm(x3.z, x3.w, 0x7632);
        uint4* dh = (uint4*)(Xh + row * 36 + q * 8);
        dh[0] = make_uint4(hh[0], hh[1], hh[2], hh[3]);
        dh[1] = make_uint4(hh[4], hh[5], hh[6], hh[7]);
        uint4* dl = (uint4*)(Xh + XL_OFF + row * 36 + q * 8);
        dl[0] = make_uint4(ll[0], ll[1], ll[2], ll[3]);
        dl[1] = make_uint4(ll[4], ll[5], ll[6], ll[7]);
    }

    // prefetch shift-0 weights
    uint4 pf[8];
    {
        const uint4* wsrc = (const uint4*)g_w2f;
        #pragma unroll
        for (int i = 0; i < 8; i++) pf[i] = wsrc[tid + i * 128];
    }

    float acc[2][8][4];
    #pragma unroll
    for (int mt = 0; mt < 2; mt++)
        #pragma unroll
        for (int nt = 0; nt < 8; nt++)
            #pragma unroll
            for (int v = 0; v < 4; v++) acc[mt][nt][v] = 0.0f;

    int s = w >> 1;
    int j2 = lane & 3;
    int xcol = lane >> 2;
    int ybase = (w & 1) * 4;        // y of mtile0 rows; mtile adds 2

    #pragma unroll 1
    for (int sh = 0; sh < 25; sh++) {
        {
            uint4* wd = (uint4*)Wf;
            #pragma unroll
            for (int i = 0; i < 8; i++) wd[tid + i * 128] = pf[i];
        }
        __syncthreads();
        if (sh < 24) {
            const uint4* wsrc = (const uint4*)g_w2f + (sh + 1) * 1024;
            #pragma unroll
            for (int i = 0; i < 8; i++) pf[i] = wsrc[tid + i * 128];
        }
        int ky = sh / 5, kx = sh - ky * 5;
        // row index for mtile mt, lower row: s*144 + (ybase+2mt+ky)*12 + xcol + kx
        int r0 = s * 144 + (ybase + ky) * 12 + xcol + kx;   // mt0
        int r1 = r0 + 24;                                    // mt1 (y+2)
        const unsigned* p0 = Xh + r0 * 36 + j2;
        const unsigned* p1 = Xh + r1 * 36 + j2;

        #pragma unroll
        for (int k = 0; k < 4; k++) {
            unsigned ah[2][4], al[2][4];
            {
                const unsigned* q0 = p0 + k * 8;
                const unsigned* q1 = q0 + 12 * 36;    // y+1 row
                ah[0][0] = q0[0]; ah[0][2] = q0[4];
                ah[0][1] = q1[0]; ah[0][3] = q1[4];
                al[0][0] = q0[XL_OFF]; al[0][2] = q0[XL_OFF + 4];
                al[0][1] = q1[XL_OFF]; al[0][3] = q1[XL_OFF + 4];
                const unsigned* q2 = p1 + k * 8;
                const unsigned* q3 = q2 + 12 * 36;
                ah[1][0] = q2[0]; ah[1][2] = q2[4];
                ah[1][1] = q3[0]; ah[1][3] = q3[4];
                al[1][0] = q2[XL_OFF]; al[1][2] = q2[XL_OFF + 4];
                al[1][1] = q3[XL_OFF]; al[1][3] = q3[XL_OFF + 4];
            }
            const unsigned long long* wk = Wf + k * 32 + lane;
            #pragma unroll
            for (int nt = 0; nt < 8; nt++) {
                unsigned long long bh = wk[nt * 128];
                unsigned long long bl = wk[1024 + nt * 128];
                unsigned bh0 = (unsigned)bh, bh1 = (unsigned)(bh >> 32);
                unsigned bl0 = (unsigned)bl, bl1 = (unsigned)(bl >> 32);
                MMA_BF16(acc[0][nt], ah[0], bh0, bh1);
                MMA_BF16(acc[1][nt], ah[1], bh0, bh1);
                MMA_BF16(acc[0][nt], al[0], bh0, bh1);
                MMA_BF16(acc[1][nt], al[1], bh0, bh1);
                MMA_BF16(acc[0][nt], ah[0], bl0, bl1);
                MMA_BF16(acc[1][nt], ah[1], bl0, bl1);
            }
        }
        __syncthreads();
    }

    // epilogue: y-pool in-thread (c0/c2 are y-neighbors), x-pool via shfl 4
    float* h2 = g_h2 + (n0 + s) * 1024;
    bool wr = ((lane >> 2) & 1) == 0;
    #pragma unroll
    for (int mt = 0; mt < 2; mt++) {
        #pragma unroll
        for (int nt = 0; nt < 8; nt++) {
            float* c = acc[mt][nt];
            float yp0 = fmaxf(c[0], c[2]);
            float yp1 = fmaxf(c[1], c[3]);
            float q0 = fmaxf(yp0, __shfl_xor_sync(0xffffffffu, yp0, 4));
            float q1 = fmaxf(yp1, __shfl_xor_sync(0xffffffffu, yp1, 4));
            if (wr) {
                int co0 = nt * 8 + (lane & 3) * 2;
                float v0 = fmaxf(q0 + g_b2[co0], 0.0f);
                float v1 = fmaxf(q1 + g_b2[co0 + 1], 0.0f);
                int py = (w & 1) * 2 + mt;
                int px = (lane >> 2) >> 1;
                int fb0 = co0 * 16 + py * 4 + px;
                h2[fb0] = v0;
                atomicAdd(&g_stat3[fb0], v0 * (1.0f / 2048.0f));
                h2[fb0 + 16] = v1;
                atomicAdd(&g_stat3[fb0 + 16], v1 * (1.0f / 2048.0f));
            }
        }
    }
}

// ======================= kernel 6: linear params =============================
__global__ void wl_kernel(const float* __restrict__ w0, const float* __restrict__ wS2,
                          const float* __restrict__ wG, const float* __restrict__ weta,
                          const float* __restrict__ wM, const float* __restrict__ b0,
                          const float* __restrict__ bS2, const float* __restrict__ bG,
                          const float* __restrict__ beta) {
    int idx = blockIdx.x * 256 + threadIdx.x;
    if (idx < 10240) {
        int i = idx & 1023;
        float M = fmaxf(wM[idx], g_stat3[i]);
        g_wl[idx] = scinol(w0[idx], wS2[idx], wG[idx], weta[idx], M, wS2[idx] != 0.0f);
    } else if (idx < 10250) {
        int j = idx - 10240;
        g_bl[j] = scinol(b0[j], bS2[j], bG[j], beta[j], 1.0f, bS2[j] != 0.0f);
    }
}

// ======================= kernel 7: linear ====================================
__global__ void __launch_bounds__(256) linear_kernel(float* __restrict__ out) {
    __shared__ float w_s[10240];
    __shared__ float b_s[16];
    for (int i = threadIdx.x; i < 10240; i += 256) w_s[i] = g_wl[i];
    if (threadIdx.x < 10) b_s[threadIdx.x] = g_bl[threadIdx.x];
    __syncthreads();
    int warp = threadIdx.x >> 5, lane = threadIdx.x & 31;
    for (int n = blockIdx.x * 8 + warp; n < 2048; n += 64 * 8) {
        const float* h = g_h2 + n * 1024;
        float hv[32];
        #pragma unroll
        for (int j = 0; j < 32; j++) hv[j] = h[lane + j * 32];
        #pragma unroll 1
        for (int o = 0; o < 10; o++) {
            float sv = 0.0f;
            #pragma unroll
            for (int j = 0; j < 32; j++) sv = fmaf(hv[j], w_s[o * 1024 + lane + j * 32], sv);
            #pragma unroll
            for (int off = 16; off; off >>= 1) sv += __shfl_xor_sync(0xffffffffu, sv, off);
            if (lane == 0) out[n * 10 + o] = sv + b_s[o];
        }
    }
}

// ======================= launch ==============================================
extern "C" void kernel_launch(void* const* d_in, const int* in_sizes, int n_in,
                              void* d_out, int out_size) {
    const float* x = (const float*)d_in[0];
    const float* c1[9]; for (int i = 0; i < 9; i++) c1[i] = (const float*)d_in[1 + i];
    const float* c2[9]; for (int i = 0; i < 9; i++) c2[i] = (const float*)d_in[10 + i];
    const float* lp[9]; for (int i = 0; i < 9; i++) lp[i] = (const float*)d_in[19 + i];
    float* out = (float*)d_out;

    cudaFuncSetAttribute(conv2_mma_kernel, cudaFuncAttributeMaxDynamicSharedMemorySize,
                         C2_SMEM);

    zero_stats_kernel<<<1, 1024>>>();
    stat1_kernel<<<2048, 256>>>(x);
    w1_kernel<<<7, 256>>>(c1[0], c1[1], c1[2], c1[3], c1[4], c1[5], c1[6], c1[7], c1[8]);
    conv1_kernel<<<2048, 256>>>(x);
    w2_kernel<<<401, 256>>>(c2[0], c2[1], c2[2], c2[3], c2[4], c2[5], c2[6], c2[7], c2[8]);
    conv2_mma_kernel<<<1024, 128, C2_SMEM>>>();
    wl_kernel<<<41, 256>>>(lp[0], lp[1], lp[2], lp[3], lp[4], lp[5], lp[6], lp[7], lp[8]);
    linear_kernel<<<64, 256>>>(out);
}